// round 2
// baseline (speedup 1.0000x reference)
#include <cuda_runtime.h>
#include <cstdint>
#include <cstddef>

#define DK  256       // feature dim (D_IN == D_OUT == 256)
#define KCH 2048      // kernel2: nodes per split-K CTA

// Scratch for y = (nodes@Wt.T + bt) * sigmoid(nodes@Wg.T + bg)   [N, 256] fp32
__device__ float g_y[200000 * 256];

__device__ __forceinline__ uint32_t f2tf(float x) {
    uint32_t u;
    asm("cvt.rna.tf32.f32 %0, %1;" : "=r"(u) : "f"(x));
    return u;
}

__device__ __forceinline__ void mma_tf32(float c[4], const uint32_t a[4],
                                         uint32_t b0, uint32_t b1) {
    asm volatile(
        "mma.sync.aligned.m16n8k8.row.col.f32.tf32.tf32.f32 "
        "{%0,%1,%2,%3},{%4,%5,%6,%7},{%8,%9},{%0,%1,%2,%3};"
        : "+f"(c[0]), "+f"(c[1]), "+f"(c[2]), "+f"(c[3])
        : "r"(a[0]), "r"(a[1]), "r"(a[2]), "r"(a[3]), "r"(b0), "r"(b1));
}

__device__ __forceinline__ float sigmoidf_(float x) {
    return 1.0f / (1.0f + __expf(-x));
}

// ---------------------------------------------------------------------------
// Kernel 1: y[n,d] = (nodes[n,:]@Wt[d,:] + bt[d]) * sigmoid(nodes[n,:]@Wg[d,:] + bg[d])
// CTA tile: 128 (nodes) x 64 (d), both matrices. 512 threads = 16 warps (4m x 4n),
// warp tile 32x16 per matrix. K=256 in 8 chunks of 32, register-staged pipeline.
// grid = (4 d-tiles fastest, mtiles) so sibling d-tiles hit the nodes tile in L2.
// ---------------------------------------------------------------------------
__global__ __launch_bounds__(512, 1)
void k1_fused(const float* __restrict__ nodes,
              const float* __restrict__ Wt, const float* __restrict__ bt,
              const float* __restrict__ Wg, const float* __restrict__ bg,
              int Nn)
{
    __shared__ float sA [128 * 36];   // nodes tile [128][32], pad 36 (bank = 4r+c unique)
    __shared__ float sBt[ 64 * 36];   // Wt tile    [64][32]
    __shared__ float sBg[ 64 * 36];   // Wg tile    [64][32]
    __shared__ float sbt[64];
    __shared__ float sbg[64];

    const int tid  = threadIdx.x;
    const int lane = tid & 31;
    const int warp = tid >> 5;
    const int g    = lane >> 2;   // groupID 0..7
    const int tg   = lane & 3;    // thread-in-group 0..3
    const int wm   = warp & 3;    // 4 m-warps, 32 rows each
    const int wn   = warp >> 2;   // 4 n-warps, 16 cols each

    const int d0 = blockIdx.x * 64;
    const int m0 = blockIdx.y * 128;

    if (tid < 64)       sbt[tid]      = bt[d0 + tid];
    else if (tid < 128) sbg[tid - 64] = bg[d0 + tid - 64];

    float accT[2][2][4];
    float accG[2][2][4];
    #pragma unroll
    for (int i = 0; i < 2; i++)
        #pragma unroll
        for (int j = 0; j < 2; j++)
            #pragma unroll
            for (int q = 0; q < 4; q++) { accT[i][j][q] = 0.f; accG[i][j][q] = 0.f; }

    const int ar  = tid >> 3;  // 0..63
    const int ac4 = tid & 7;   // float4 column within 32-wide chunk
    float4 rA[2], rBt, rBg;

#define K1_LDG(KC) {                                                                       \
    const int kb_ = (KC) * 32;                                                             \
    for (int i_ = 0; i_ < 2; i_++) {                                                       \
        const int gr_ = m0 + ar + i_ * 64;                                                 \
        rA[i_] = (gr_ < Nn) ? *(const float4*)(nodes + (size_t)gr_ * DK + kb_ + ac4 * 4)   \
                            : make_float4(0.f, 0.f, 0.f, 0.f);                             \
    }                                                                                      \
    rBt = *(const float4*)(Wt + (size_t)(d0 + ar) * DK + kb_ + ac4 * 4);                   \
    rBg = *(const float4*)(Wg + (size_t)(d0 + ar) * DK + kb_ + ac4 * 4);                   \
}

#define K1_STS() {                                                                         \
    for (int i_ = 0; i_ < 2; i_++) {                                                       \
        float4 t_;                                                                         \
        t_.x = __uint_as_float(f2tf(rA[i_].x));                                            \
        t_.y = __uint_as_float(f2tf(rA[i_].y));                                            \
        t_.z = __uint_as_float(f2tf(rA[i_].z));                                            \
        t_.w = __uint_as_float(f2tf(rA[i_].w));                                            \
        *(float4*)(sA + (ar + i_ * 64) * 36 + ac4 * 4) = t_;                               \
    }                                                                                      \
    {                                                                                      \
        float4 t1_, t2_;                                                                   \
        t1_.x = __uint_as_float(f2tf(rBt.x)); t1_.y = __uint_as_float(f2tf(rBt.y));        \
        t1_.z = __uint_as_float(f2tf(rBt.z)); t1_.w = __uint_as_float(f2tf(rBt.w));        \
        t2_.x = __uint_as_float(f2tf(rBg.x)); t2_.y = __uint_as_float(f2tf(rBg.y));        \
        t2_.z = __uint_as_float(f2tf(rBg.z)); t2_.w = __uint_as_float(f2tf(rBg.w));        \
        *(float4*)(sBt + ar * 36 + ac4 * 4) = t1_;                                         \
        *(float4*)(sBg + ar * 36 + ac4 * 4) = t2_;                                         \
    }                                                                                      \
}

    K1_LDG(0);
    #pragma unroll 1
    for (int kc = 0; kc < 8; ++kc) {
        K1_STS();
        __syncthreads();
        if (kc < 7) { K1_LDG(kc + 1); }

        #pragma unroll
        for (int ks = 0; ks < 4; ++ks) {
            uint32_t a[2][4];
            #pragma unroll
            for (int mf = 0; mf < 2; mf++) {
                const float* p = sA + (wm * 32 + mf * 16 + g) * 36 + ks * 8 + tg;
                a[mf][0] = __float_as_uint(p[0]);
                a[mf][1] = __float_as_uint(p[8 * 36]);
                a[mf][2] = __float_as_uint(p[4]);
                a[mf][3] = __float_as_uint(p[8 * 36 + 4]);
            }
            #pragma unroll
            for (int nf = 0; nf < 2; nf++) {
                const int nb = (wn * 16 + nf * 8 + g) * 36 + ks * 8 + tg;
                const uint32_t b0t = __float_as_uint(sBt[nb]);
                const uint32_t b1t = __float_as_uint(sBt[nb + 4]);
                const uint32_t b0g = __float_as_uint(sBg[nb]);
                const uint32_t b1g = __float_as_uint(sBg[nb + 4]);
                #pragma unroll
                for (int mf = 0; mf < 2; mf++) {
                    mma_tf32(accT[mf][nf], a[mf], b0t, b1t);
                    mma_tf32(accG[mf][nf], a[mf], b0g, b1g);
                }
            }
        }
        __syncthreads();
    }

    // Epilogue: bias + sigmoid gating, write y
    #pragma unroll
    for (int mf = 0; mf < 2; mf++) {
        const int r0 = m0 + wm * 32 + mf * 16 + g;
        #pragma unroll
        for (int nf = 0; nf < 2; nf++) {
            const int dl  = wn * 16 + nf * 8 + 2 * tg;
            const float bt0 = sbt[dl], bt1 = sbt[dl + 1];
            const float bg0 = sbg[dl], bg1 = sbg[dl + 1];
            if (r0 < Nn) {
                float2 v;
                v.x = (accT[mf][nf][0] + bt0) * sigmoidf_(accG[mf][nf][0] + bg0);
                v.y = (accT[mf][nf][1] + bt1) * sigmoidf_(accG[mf][nf][1] + bg1);
                *(float2*)(g_y + (size_t)r0 * DK + d0 + dl) = v;
            }
            if (r0 + 8 < Nn) {
                float2 v;
                v.x = (accT[mf][nf][2] + bt0) * sigmoidf_(accG[mf][nf][2] + bg0);
                v.y = (accT[mf][nf][3] + bt1) * sigmoidf_(accG[mf][nf][3] + bg1);
                *(float2*)(g_y + (size_t)(r0 + 8) * DK + d0 + dl) = v;
            }
        }
    }
#undef K1_LDG
#undef K1_STS
}

// ---------------------------------------------------------------------------
// Kernel 2: out[b,d] += mask[b, k0:k0+KCH] @ y[k0:k0+KCH, d]   (split-K + atomics)
// CTA tile: 128 (b) x 64 (d), K-chunk KCH per CTA in sub-chunks of 32.
// 512 threads = 16 warps (4m x 4n), warp tile 32x16.
// ---------------------------------------------------------------------------
__global__ __launch_bounds__(512, 1)
void k2_scatter(const int* __restrict__ mask, float* __restrict__ out, int Nn)
{
    __shared__ float sA[128 * 36];  // mask tile [128 b][32 k], pad 36
    __shared__ float sB[ 32 * 72];  // y tile    [32 k][64 d], pad 72 (bank = 8tg+g unique)

    const int tid  = threadIdx.x;
    const int lane = tid & 31;
    const int warp = tid >> 5;
    const int g    = lane >> 2;
    const int tg   = lane & 3;
    const int wm   = warp & 3;
    const int wn   = warp >> 2;

    const int b0 = blockIdx.x * 128;
    const int d0 = blockIdx.y * 64;
    const int k0 = blockIdx.z * KCH;

    float acc[2][2][4];
    #pragma unroll
    for (int i = 0; i < 2; i++)
        #pragma unroll
        for (int j = 0; j < 2; j++)
            #pragma unroll
            for (int q = 0; q < 4; q++) acc[i][j][q] = 0.f;

    const int mr  = tid >> 3, mc4 = tid & 7;    // mask staging: 2 rows of 64
    const int yr  = tid >> 4, yc4 = tid & 15;   // y staging: 32 rows x 16 float4

    int nch = (Nn - k0 + 31) / 32;              // N is a multiple of 32 here
    if (nch > KCH / 32) nch = KCH / 32;
    if (nch <= 0) return;

    int4   rM[2];
    float4 rY;

#define K2_LDG(KC) {                                                                         \
    const int kb_ = k0 + (KC) * 32;                                                          \
    for (int i_ = 0; i_ < 2; i_++)                                                           \
        rM[i_] = *(const int4*)(mask + (size_t)(b0 + mr + i_ * 64) * Nn + kb_ + mc4 * 4);    \
    rY = ((kb_ + yr) < Nn)                                                                   \
         ? *(const float4*)(g_y + (size_t)(kb_ + yr) * DK + d0 + yc4 * 4)                    \
         : make_float4(0.f, 0.f, 0.f, 0.f);                                                  \
}

#define K2_STS() {                                                                           \
    for (int i_ = 0; i_ < 2; i_++) {                                                         \
        float4 t_;                                                                           \
        t_.x = (float)rM[i_].x; t_.y = (float)rM[i_].y;                                      \
        t_.z = (float)rM[i_].z; t_.w = (float)rM[i_].w;                                      \
        *(float4*)(sA + (mr + i_ * 64) * 36 + mc4 * 4) = t_;                                 \
    }                                                                                        \
    {                                                                                        \
        float4 t_;                                                                           \
        t_.x = __uint_as_float(f2tf(rY.x)); t_.y = __uint_as_float(f2tf(rY.y));              \
        t_.z = __uint_as_float(f2tf(rY.z)); t_.w = __uint_as_float(f2tf(rY.w));              \
        *(float4*)(sB + yr * 72 + yc4 * 4) = t_;                                             \
    }                                                                                        \
}

    K2_LDG(0);
    #pragma unroll 1
    for (int kc = 0; kc < nch; ++kc) {
        K2_STS();
        __syncthreads();
        if (kc + 1 < nch) { K2_LDG(kc + 1); }

        #pragma unroll
        for (int ks = 0; ks < 4; ++ks) {
            uint32_t a[2][4];
            #pragma unroll
            for (int mf = 0; mf < 2; mf++) {
                const float* p = sA + (wm * 32 + mf * 16 + g) * 36 + ks * 8 + tg;
                a[mf][0] = __float_as_uint(p[0]);
                a[mf][1] = __float_as_uint(p[8 * 36]);
                a[mf][2] = __float_as_uint(p[4]);
                a[mf][3] = __float_as_uint(p[8 * 36 + 4]);
            }
            #pragma unroll
            for (int nf = 0; nf < 2; nf++) {
                const int col = wn * 16 + nf * 8 + g;
                const uint32_t b0r = __float_as_uint(sB[(ks * 8 + tg) * 72 + col]);
                const uint32_t b1r = __float_as_uint(sB[(ks * 8 + tg + 4) * 72 + col]);
                #pragma unroll
                for (int mf = 0; mf < 2; mf++)
                    mma_tf32(acc[mf][nf], a[mf], b0r, b1r);
            }
        }
        __syncthreads();
    }

    // Epilogue: atomic accumulate split-K partials
    #pragma unroll
    for (int mf = 0; mf < 2; mf++) {
        const int r = b0 + wm * 32 + mf * 16 + g;
        #pragma unroll
        for (int nf = 0; nf < 2; nf++) {
            const int c = d0 + wn * 16 + nf * 8 + 2 * tg;
            atomicAdd(out + (size_t)r * DK + c,           acc[mf][nf][0]);
            atomicAdd(out + (size_t)r * DK + c + 1,       acc[mf][nf][1]);
            atomicAdd(out + (size_t)(r + 8) * DK + c,     acc[mf][nf][2]);
            atomicAdd(out + (size_t)(r + 8) * DK + c + 1, acc[mf][nf][3]);
        }
    }
#undef K2_LDG
#undef K2_STS
}

__global__ void kzero(float* __restrict__ o, int n) {
    const int i = blockIdx.x * 256 + threadIdx.x;
    if (i < n) o[i] = 0.f;
}

extern "C" void kernel_launch(void* const* d_in, const int* in_sizes, int n_in,
                              void* d_out, int out_size)
{
    const float* nodes = (const float*)d_in[0];
    const int*   mask  = (const int*)  d_in[1];
    const float* Wt    = (const float*)d_in[2];
    const float* bt    = (const float*)d_in[3];
    const float* Wg    = (const float*)d_in[4];
    const float* bg    = (const float*)d_in[5];
    float* out = (float*)d_out;

    const int Nn = in_sizes[0] / DK;      // 200000
    const int Bb = in_sizes[1] / Nn;      // 256

    const int mtiles = (Nn + 127) / 128;
    const int S      = (Nn + KCH - 1) / KCH;

    kzero<<<(out_size + 255) / 256, 256>>>(out, out_size);
    k1_fused<<<dim3(4, mtiles), 512>>>(nodes, Wt, bt, Wg, bg, Nn);
    k2_scatter<<<dim3(Bb / 128, 4, S), 512>>>(mask, out, Nn);
}

// round 7
// speedup vs baseline: 2.2547x; 2.2547x over previous
#include <cuda_runtime.h>
#include <cuda_bf16.h>
#include <cstdint>
#include <cstddef>

#define DK 256        // feature dim
#define NC 32         // nodes per chunk (GEMM2 K)
#define ZS 74         // split-K CTAs per d-tile (x2 d-tiles = 148 CTAs)

// ---- smem layout (byte offsets / strides; padding chosen conflict-free) ----
#define W_STRIDE  528                      // 256 bf16 + 8 pad
#define ND_STRIDE 528
#define MK_STRIDE 160                      // 32 int32 + 8 pad
#define YT_STRIDE 80                       // 32 bf16 + 8 pad
#define OFF_WT 0
#define OFF_WG 67584                       // 128*528
#define OFF_ND 135168                      // + 128*528
#define OFF_MK 152064                      // + 32*528
#define OFF_YT 193024                      // + 256*160
#define SMEM_TOTAL 203264                  // + 128*80

static __device__ __forceinline__ uint32_t smem_u32(const void* p) {
    uint32_t a;
    asm("{ .reg .u64 t; cvta.to.shared.u64 t, %1; cvt.u32.u64 %0, t; }" : "=r"(a) : "l"(p));
    return a;
}

#define LDSM_X4(R, addr)                                                      \
    asm volatile("ldmatrix.sync.aligned.m8n8.x4.shared.b16 {%0,%1,%2,%3}, [%4];" \
                 : "=r"((R)[0]), "=r"((R)[1]), "=r"((R)[2]), "=r"((R)[3])     \
                 : "r"(addr))

#define MMA_BF16(C, A, b0, b1)                                                \
    asm volatile("mma.sync.aligned.m16n8k16.row.col.f32.bf16.bf16.f32 "       \
                 "{%0,%1,%2,%3},{%4,%5,%6,%7},{%8,%9},{%0,%1,%2,%3};"         \
                 : "+f"((C)[0]), "+f"((C)[1]), "+f"((C)[2]), "+f"((C)[3])     \
                 : "r"((A)[0]), "r"((A)[1]), "r"((A)[2]), "r"((A)[3]),        \
                   "r"(b0), "r"(b1))

#define CP16(dst, src)                                                        \
    asm volatile("cp.async.cg.shared.global [%0], [%1], 16;"                  \
                 :: "r"(dst), "l"(src) : "memory")
#define CP_COMMIT() asm volatile("cp.async.commit_group;" ::: "memory")
#define CP_WAIT0()  asm volatile("cp.async.wait_group 0;" ::: "memory")

// mask int {0,1} pair -> packed bf16x2 {1.0 or 0.0}: exact, 2 IMADs
static __device__ __forceinline__ uint32_t cvtm(int2 v) {
    return (uint32_t)v.x * 0x3F80u + (uint32_t)v.y * 0x3F800000u;
}

static __device__ __forceinline__ void store_bf4(char* p, float4 v) {
    __nv_bfloat162 lo = __floats2bfloat162_rn(v.x, v.y);
    __nv_bfloat162 hi = __floats2bfloat162_rn(v.z, v.w);
    uint2 u;
    u.x = *reinterpret_cast<uint32_t*>(&lo);
    u.y = *reinterpret_cast<uint32_t*>(&hi);
    *reinterpret_cast<uint2*>(p) = u;
}

static __device__ __forceinline__ float sigm(float x) { return 1.0f / (1.0f + __expf(-x)); }

// ---------------------------------------------------------------------------
// Fused kernel. Per CTA (z, d-tile): for each node chunk (strided by ZS):
//   GEMM1: yT[128d x 32n] = W[128d x 256k] @ nodes_chunk^T       (bf16 mma)
//   gate epilogue -> yT bf16 smem
//   GEMM2: acc[256b x 128d] += mask_chunk[256b x 32n] @ yT       (bf16 mma)
// Persistent register acc; final atomicAdd into out.
// ---------------------------------------------------------------------------
__global__ __launch_bounds__(512, 1)
void fused_agg(const float* __restrict__ nodes, const int* __restrict__ mask,
               const float* __restrict__ Wt, const float* __restrict__ bt,
               const float* __restrict__ Wg, const float* __restrict__ bg,
               float* __restrict__ out, int Nn)
{
    extern __shared__ char sm[];
    const uint32_t sb = smem_u32(sm);
    const int tid  = threadIdx.x;
    const int lane = tid & 31;
    const int wid  = tid >> 5;
    const int g    = lane >> 2;
    const int tg   = lane & 3;
    const int z    = blockIdx.x;
    const int d0   = blockIdx.y * 128;

    // GEMM1 warp roles: 8 m-warps (16 d rows) x 2 n-warps (16 n cols)
    const int wm = wid & 7;
    const int wn = wid >> 3;
    // GEMM2 warp roles: 4 m-warps (64 b rows) x 4 n-warps (32 d cols)
    const int wm2 = wid & 3;
    const int wn2 = wid >> 2;

    // Per-thread gate biases for GEMM1 epilogue rows (d = wm*16+g, +8)
    const float bt0 = bt[d0 + wm * 16 + g];
    const float bt1 = bt[d0 + wm * 16 + 8 + g];
    const float bg0 = bg[d0 + wm * 16 + g];
    const float bg1 = bg[d0 + wm * 16 + 8 + g];

    // Persistent GEMM2 accumulators: 4 mfrag x 4 nfrag x 4
    float acc2[4][4][4];
    #pragma unroll
    for (int i = 0; i < 4; i++)
        #pragma unroll
        for (int j = 0; j < 4; j++)
            #pragma unroll
            for (int q = 0; q < 4; q++) acc2[i][j][q] = 0.f;

    const int NCHK = Nn / NC;

    // ---- prologue: issue cp.async for mask(chunk z) ----
    {
        const int n0 = z * NC;
        #pragma unroll
        for (int i = 0; i < 4; i++) {
            int o = tid + i * 512;            // 2048 ops: 256 rows x 8 segs
            int row = o >> 3, seg = o & 7;
            CP16(sb + OFF_MK + row * MK_STRIDE + seg * 16,
                 (const char*)(mask + (size_t)row * Nn + n0) + seg * 16);
        }
        CP_COMMIT();
    }

    // ---- stage resident W (both matrices, f32 -> bf16, padded rows) ----
    #pragma unroll
    for (int i = 0; i < 16; i++) {
        int f4  = tid + i * 512;              // 8192 float4 per matrix
        int row = f4 >> 6;
        int col = (f4 & 63) * 4;
        store_bf4(sm + OFF_WT + row * W_STRIDE + col * 2,
                  *(const float4*)(Wt + (size_t)(d0 + row) * DK + col));
        store_bf4(sm + OFF_WG + row * W_STRIDE + col * 2,
                  *(const float4*)(Wg + (size_t)(d0 + row) * DK + col));
    }

    // ldmatrix lane addresses (row patterns fixed; k advances per step)
    const uint32_t aWt = sb + OFF_WT + (wm * 16 + (lane & 15)) * W_STRIDE + ((lane >> 4) << 4);
    const uint32_t aWg = aWt + (OFF_WG - OFF_WT);
    const uint32_t bNd = sb + OFF_ND
                       + (wn * 16 + (lane & 7) + ((lane >> 4) << 3)) * ND_STRIDE
                       + (((lane >> 3) & 1) << 4);
    const uint32_t bY0 = sb + OFF_YT
                       + (wn2 * 32 + (lane & 7) + ((lane >> 4) << 3)) * YT_STRIDE
                       + (((lane >> 3) & 1) << 4);
    const uint32_t bY1 = bY0 + 16 * YT_STRIDE;

    for (int c = z; c < NCHK; c += ZS) {
        const int n0 = c * NC;

        // ---- stage nodes chunk [32 n x 256 k], f32 -> bf16 ----
        {
            const int row = tid >> 4, c16 = tid & 15;
            const float* src = nodes + (size_t)(n0 + row) * DK + c16 * 4;
            char* dst = sm + OFF_ND + row * ND_STRIDE + c16 * 8;
            #pragma unroll
            for (int i = 0; i < 4; i++) {
                float4 v = (n0 + row < Nn) ? *(const float4*)(src + i * 64)
                                           : make_float4(0.f, 0.f, 0.f, 0.f);
                store_bf4(dst + i * 128, v);
            }
        }
        __syncthreads();   // nodes (+W on iter 0) visible

        // ---- GEMM1: yT = W @ nodes^T  (M=128, N=32, K=256) ----
        float aT0[4] = {0,0,0,0}, aT1[4] = {0,0,0,0};
        float aG0[4] = {0,0,0,0}, aG1[4] = {0,0,0,0};
        #pragma unroll
        for (int ks = 0; ks < 16; ks++) {
            uint32_t At[4], Ag[4], Bn[4];
            LDSM_X4(At, aWt + ks * 32);
            LDSM_X4(Ag, aWg + ks * 32);
            LDSM_X4(Bn, bNd + ks * 32);
            MMA_BF16(aT0, At, Bn[0], Bn[1]);
            MMA_BF16(aT1, At, Bn[2], Bn[3]);
            MMA_BF16(aG0, Ag, Bn[0], Bn[1]);
            MMA_BF16(aG1, Ag, Bn[2], Bn[3]);
        }

        // ---- epilogue: y = (t+bt)*sigmoid(g+bg) -> yT smem bf16 ----
        {
            char* r0 = sm + OFF_YT + (wm * 16 + g) * YT_STRIDE + (wn * 16 + 2 * tg) * 2;
            char* r1 = r0 + 8 * YT_STRIDE;
            __nv_bfloat162 h;
            h = __floats2bfloat162_rn((aT0[0] + bt0) * sigm(aG0[0] + bg0),
                                      (aT0[1] + bt0) * sigm(aG0[1] + bg0));
            *(uint32_t*)r0 = *reinterpret_cast<uint32_t*>(&h);
            h = __floats2bfloat162_rn((aT0[2] + bt1) * sigm(aG0[2] + bg1),
                                      (aT0[3] + bt1) * sigm(aG0[3] + bg1));
            *(uint32_t*)r1 = *reinterpret_cast<uint32_t*>(&h);
            h = __floats2bfloat162_rn((aT1[0] + bt0) * sigm(aG1[0] + bg0),
                                      (aT1[1] + bt0) * sigm(aG1[1] + bg0));
            *(uint32_t*)(r0 + 16) = *reinterpret_cast<uint32_t*>(&h);
            h = __floats2bfloat162_rn((aT1[2] + bt1) * sigm(aG1[2] + bg1),
                                      (aT1[3] + bt1) * sigm(aG1[3] + bg1));
            *(uint32_t*)(r1 + 16) = *reinterpret_cast<uint32_t*>(&h);
        }

        CP_WAIT0();        // mask(c) landed (issued one "phase" earlier)
        __syncthreads();   // yT + mask visible to all warps

        // ---- GEMM2: acc += mask @ yT  (M=256, N=128, K=32) ----
        #pragma unroll
        for (int ks = 0; ks < 2; ks++) {
            uint32_t Y0[4], Y1[4];
            LDSM_X4(Y0, bY0 + ks * 32);
            LDSM_X4(Y1, bY1 + ks * 32);
            const int kk = ks * 16;
            #pragma unroll
            for (int mf = 0; mf < 4; mf++) {
                const char* mrow = sm + OFF_MK + (wm2 * 64 + mf * 16 + g) * MK_STRIDE;
                uint32_t A[4];
                A[0] = cvtm(*(const int2*)(mrow + (kk + 2 * tg) * 4));
                A[1] = cvtm(*(const int2*)(mrow + 8 * MK_STRIDE + (kk + 2 * tg) * 4));
                A[2] = cvtm(*(const int2*)(mrow + (kk + 8 + 2 * tg) * 4));
                A[3] = cvtm(*(const int2*)(mrow + 8 * MK_STRIDE + (kk + 8 + 2 * tg) * 4));
                MMA_BF16(acc2[mf][0], A, Y0[0], Y0[1]);
                MMA_BF16(acc2[mf][1], A, Y0[2], Y0[3]);
                MMA_BF16(acc2[mf][2], A, Y1[0], Y1[1]);
                MMA_BF16(acc2[mf][3], A, Y1[2], Y1[3]);
            }
        }
        __syncthreads();   // GEMM2 done: mask/yT/nodes smem free

        // ---- prefetch mask(c+ZS): overlaps next nodes staging + GEMM1 ----
        if (c + ZS < NCHK) {
            const int nn = (c + ZS) * NC;
            #pragma unroll
            for (int i = 0; i < 4; i++) {
                int o = tid + i * 512;
                int row = o >> 3, seg = o & 7;
                CP16(sb + OFF_MK + row * MK_STRIDE + seg * 16,
                     (const char*)(mask + (size_t)row * Nn + nn) + seg * 16);
            }
            CP_COMMIT();
        }
    }

    // ---- drain: atomic-accumulate split-K partials ----
    #pragma unroll
    for (int mf = 0; mf < 4; mf++) {
        const int r = wm2 * 64 + mf * 16 + g;
        #pragma unroll
        for (int nf = 0; nf < 4; nf++) {
            const int cb = d0 + wn2 * 32 + nf * 8 + 2 * tg;
            atomicAdd(out + (size_t)r * DK + cb,           acc2[mf][nf][0]);
            atomicAdd(out + (size_t)r * DK + cb + 1,       acc2[mf][nf][1]);
            atomicAdd(out + (size_t)(r + 8) * DK + cb,     acc2[mf][nf][2]);
            atomicAdd(out + (size_t)(r + 8) * DK + cb + 1, acc2[mf][nf][3]);
        }
    }
}

__global__ void kzero(float* __restrict__ o, int n) {
    const int i = blockIdx.x * 256 + threadIdx.x;
    if (i < n) o[i] = 0.f;
}

extern "C" void kernel_launch(void* const* d_in, const int* in_sizes, int n_in,
                              void* d_out, int out_size)
{
    const float* nodes = (const float*)d_in[0];
    const int*   mask  = (const int*)  d_in[1];
    const float* Wt    = (const float*)d_in[2];
    const float* bt    = (const float*)d_in[3];
    const float* Wg    = (const float*)d_in[4];
    const float* bg    = (const float*)d_in[5];
    float* out = (float*)d_out;

    const int Nn = in_sizes[0] / DK;   // 200000

    cudaFuncSetAttribute(fused_agg, cudaFuncAttributeMaxDynamicSharedMemorySize, SMEM_TOTAL);

    kzero<<<(out_size + 255) / 256, 256>>>(out, out_size);
    fused_agg<<<dim3(ZS, 2), 512, SMEM_TOTAL>>>(nodes, mask, Wt, bt, Wg, bg, out, Nn);
}

// round 8
// speedup vs baseline: 2.6887x; 1.1925x over previous
#include <cuda_runtime.h>
#include <cuda_bf16.h>
#include <cstdint>
#include <cstddef>

#define DK 256        // feature dim
#define NC 32         // nodes per chunk (GEMM2 K)
#define ZS 74         // split-K CTAs per d-tile (x2 d-tiles = 148 CTAs)

// ---- smem layout (byte offsets / strides; padding chosen conflict-free) ----
#define W_STRIDE  528                      // 256 bf16 + 8 pad
#define ND_STRIDE 528
#define MK_STRIDE 160                      // 32 int32 + 8 pad
#define YT_STRIDE 80                       // 32 bf16 + 8 pad
#define OFF_WT 0
#define OFF_WG 67584                       // 128*528
#define OFF_ND 135168                      // + 128*528
#define OFF_MK 152064                      // + 32*528
#define OFF_YT 193024                      // + 256*160
#define SMEM_TOTAL 203264                  // + 128*80

static __device__ __forceinline__ uint32_t smem_u32(const void* p) {
    uint32_t a;
    asm("{ .reg .u64 t; cvta.to.shared.u64 t, %1; cvt.u32.u64 %0, t; }" : "=r"(a) : "l"(p));
    return a;
}

#define LDSM_X4(R, addr)                                                      \
    asm volatile("ldmatrix.sync.aligned.m8n8.x4.shared.b16 {%0,%1,%2,%3}, [%4];" \
                 : "=r"((R)[0]), "=r"((R)[1]), "=r"((R)[2]), "=r"((R)[3])     \
                 : "r"(addr))

#define MMA_BF16(C, A, b0, b1)                                                \
    asm volatile("mma.sync.aligned.m16n8k16.row.col.f32.bf16.bf16.f32 "       \
                 "{%0,%1,%2,%3},{%4,%5,%6,%7},{%8,%9},{%0,%1,%2,%3};"         \
                 : "+f"((C)[0]), "+f"((C)[1]), "+f"((C)[2]), "+f"((C)[3])     \
                 : "r"((A)[0]), "r"((A)[1]), "r"((A)[2]), "r"((A)[3]),        \
                   "r"(b0), "r"(b1))

#define CP16(dst, src)                                                        \
    asm volatile("cp.async.cg.shared.global [%0], [%1], 16;"                  \
                 :: "r"(dst), "l"(src) : "memory")
#define CP_COMMIT() asm volatile("cp.async.commit_group;" ::: "memory")
#define CP_WAIT0()  asm volatile("cp.async.wait_group 0;" ::: "memory")

// mask int {0,1} pair -> packed bf16x2 {1.0 or 0.0}: exact, 2 IMADs
static __device__ __forceinline__ uint32_t cvtm(int2 v) {
    return (uint32_t)v.x * 0x3F80u + (uint32_t)v.y * 0x3F800000u;
}

static __device__ __forceinline__ void store_bf4(char* p, float4 v) {
    __nv_bfloat162 lo = __floats2bfloat162_rn(v.x, v.y);
    __nv_bfloat162 hi = __floats2bfloat162_rn(v.z, v.w);
    uint2 u;
    u.x = *reinterpret_cast<uint32_t*>(&lo);
    u.y = *reinterpret_cast<uint32_t*>(&hi);
    *reinterpret_cast<uint2*>(p) = u;
}

static __device__ __forceinline__ float sigm(float x) { return 1.0f / (1.0f + __expf(-x)); }

// ---------------------------------------------------------------------------
// Fused kernel. Per CTA (z, d-tile): for each node chunk (strided by ZS):
//   GEMM1: yT[128d x 32n] = W[128d x 256k] @ nodes_chunk^T       (bf16 mma)
//   gate epilogue -> yT bf16 smem
//   GEMM2: acc[256b x 128d] += mask_chunk[256b x 32n] @ yT       (bf16 mma)
// Nodes register-prefetched one chunk ahead (latency hidden under GEMM2).
// GEMM2 layout: 16 m-warps x 1 n-warp (warp tile 16b x 128d) -> mask loads
// deduplicated. Persistent register acc; final atomicAdd into out.
// ---------------------------------------------------------------------------
__global__ __launch_bounds__(512, 1)
void fused_agg(const float* __restrict__ nodes, const int* __restrict__ mask,
               const float* __restrict__ Wt, const float* __restrict__ bt,
               const float* __restrict__ Wg, const float* __restrict__ bg,
               float* __restrict__ out, int Nn)
{
    extern __shared__ char sm[];
    const uint32_t sb = smem_u32(sm);
    const int tid  = threadIdx.x;
    const int lane = tid & 31;
    const int wid  = tid >> 5;
    const int g    = lane >> 2;
    const int tg   = lane & 3;
    const int z    = blockIdx.x;
    const int d0   = blockIdx.y * 128;

    // GEMM1 warp roles: 8 m-warps (16 d rows) x 2 n-warps (16 n cols)
    const int wm = wid & 7;
    const int wn = wid >> 3;

    // Per-thread gate biases for GEMM1 epilogue rows (d = wm*16+g, +8)
    const float bt0 = bt[d0 + wm * 16 + g];
    const float bt1 = bt[d0 + wm * 16 + 8 + g];
    const float bg0 = bg[d0 + wm * 16 + g];
    const float bg1 = bg[d0 + wm * 16 + 8 + g];

    // Persistent GEMM2 accumulators: 16 n8-frags x 4 (warp tile 16b x 128d)
    float acc2[16][4];
    #pragma unroll
    for (int j = 0; j < 16; j++)
        #pragma unroll
        for (int q = 0; q < 4; q++) acc2[j][q] = 0.f;

    const int NCHK = Nn / NC;   // Nn % 32 == 0 for this problem

    // ---- prologue: issue cp.async for mask(chunk z) ----
    {
        const int n0 = z * NC;
        #pragma unroll
        for (int i = 0; i < 4; i++) {
            int o = tid + i * 512;            // 2048 ops: 256 rows x 8 segs
            int row = o >> 3, seg = o & 7;
            CP16(sb + OFF_MK + row * MK_STRIDE + seg * 16,
                 (const char*)(mask + (size_t)row * Nn + n0) + seg * 16);
        }
        CP_COMMIT();
    }

    // ---- stage resident W (both matrices, f32 -> bf16, padded rows) ----
    #pragma unroll
    for (int i = 0; i < 16; i++) {
        int f4  = tid + i * 512;              // 8192 float4 per matrix
        int row = f4 >> 6;
        int col = (f4 & 63) * 4;
        store_bf4(sm + OFF_WT + row * W_STRIDE + col * 2,
                  *(const float4*)(Wt + (size_t)(d0 + row) * DK + col));
        store_bf4(sm + OFF_WG + row * W_STRIDE + col * 2,
                  *(const float4*)(Wg + (size_t)(d0 + row) * DK + col));
    }

    // ldmatrix lane addresses
    const uint32_t aWt = sb + OFF_WT + (wm * 16 + (lane & 15)) * W_STRIDE + ((lane >> 4) << 4);
    const uint32_t aWg = aWt + (OFF_WG - OFF_WT);
    const uint32_t bNd = sb + OFF_ND
                       + (wn * 16 + (lane & 7) + ((lane >> 4) << 3)) * ND_STRIDE
                       + (((lane >> 3) & 1) << 4);
    const uint32_t bY  = sb + OFF_YT
                       + ((lane & 7) + ((lane >> 4) << 3)) * YT_STRIDE
                       + (((lane >> 3) & 1) << 4);

    // ---- nodes register staging (prefetched one chunk ahead) ----
    const int srow = tid >> 4;                // 0..31
    const int sc16 = tid & 15;                // float4 column group
    float4 rN[4];
    {
        const float* src = nodes + (size_t)(z * NC + srow) * DK + sc16 * 4;
        #pragma unroll
        for (int i = 0; i < 4; i++) rN[i] = *(const float4*)(src + i * 64);
    }

    for (int c = z; c < NCHK; c += ZS) {
        // ---- STS nodes chunk from prefetched regs (f32 -> bf16) ----
        {
            char* dst = sm + OFF_ND + srow * ND_STRIDE + sc16 * 8;
            #pragma unroll
            for (int i = 0; i < 4; i++) store_bf4(dst + i * 128, rN[i]);
        }
        __syncthreads();   // nodes (+W on iter 0) visible

        // ---- GEMM1: yT = W @ nodes^T  (M=128, N=32, K=256) ----
        float aT0[4] = {0,0,0,0}, aT1[4] = {0,0,0,0};
        float aG0[4] = {0,0,0,0}, aG1[4] = {0,0,0,0};
        #pragma unroll
        for (int ks = 0; ks < 16; ks++) {
            uint32_t At[4], Ag[4], Bn[4];
            LDSM_X4(At, aWt + ks * 32);
            LDSM_X4(Ag, aWg + ks * 32);
            LDSM_X4(Bn, bNd + ks * 32);
            MMA_BF16(aT0, At, Bn[0], Bn[1]);
            MMA_BF16(aT1, At, Bn[2], Bn[3]);
            MMA_BF16(aG0, Ag, Bn[0], Bn[1]);
            MMA_BF16(aG1, Ag, Bn[2], Bn[3]);
        }

        // ---- epilogue: y = (t+bt)*sigmoid(g+bg) -> yT smem bf16 ----
        {
            char* r0 = sm + OFF_YT + (wm * 16 + g) * YT_STRIDE + (wn * 16 + 2 * tg) * 2;
            char* r1 = r0 + 8 * YT_STRIDE;
            __nv_bfloat162 h;
            h = __floats2bfloat162_rn((aT0[0] + bt0) * sigm(aG0[0] + bg0),
                                      (aT0[1] + bt0) * sigm(aG0[1] + bg0));
            *(uint32_t*)r0 = *reinterpret_cast<uint32_t*>(&h);
            h = __floats2bfloat162_rn((aT0[2] + bt1) * sigm(aG0[2] + bg1),
                                      (aT0[3] + bt1) * sigm(aG0[3] + bg1));
            *(uint32_t*)r1 = *reinterpret_cast<uint32_t*>(&h);
            h = __floats2bfloat162_rn((aT1[0] + bt0) * sigm(aG1[0] + bg0),
                                      (aT1[1] + bt0) * sigm(aG1[1] + bg0));
            *(uint32_t*)(r0 + 16) = *reinterpret_cast<uint32_t*>(&h);
            h = __floats2bfloat162_rn((aT1[2] + bt1) * sigm(aG1[2] + bg1),
                                      (aT1[3] + bt1) * sigm(aG1[3] + bg1));
            *(uint32_t*)(r1 + 16) = *reinterpret_cast<uint32_t*>(&h);
        }

        // ---- prefetch nodes(c+ZS) into regs: latency hidden under GEMM2 ----
        if (c + ZS < NCHK) {
            const float* src = nodes + (size_t)((c + ZS) * NC + srow) * DK + sc16 * 4;
            #pragma unroll
            for (int i = 0; i < 4; i++) rN[i] = *(const float4*)(src + i * 64);
        }

        CP_WAIT0();        // mask(c) landed (issued one phase earlier)
        __syncthreads();   // yT + mask visible to all warps

        // ---- GEMM2: acc += mask @ yT  (warp tile 16b x 128d) ----
        {
            const char* mrow = sm + OFF_MK + (wid * 16 + g) * MK_STRIDE;
            #pragma unroll
            for (int ks = 0; ks < 2; ks++) {
                const int kk = ks * 16;
                uint32_t A[4];
                A[0] = cvtm(*(const int2*)(mrow + (kk + 2 * tg) * 4));
                A[1] = cvtm(*(const int2*)(mrow + 8 * MK_STRIDE + (kk + 2 * tg) * 4));
                A[2] = cvtm(*(const int2*)(mrow + (kk + 8 + 2 * tg) * 4));
                A[3] = cvtm(*(const int2*)(mrow + 8 * MK_STRIDE + (kk + 8 + 2 * tg) * 4));
                #pragma unroll
                for (int nf = 0; nf < 8; nf++) {
                    uint32_t Y[4];
                    LDSM_X4(Y, bY + nf * 16 * YT_STRIDE + ks * 32);
                    MMA_BF16(acc2[2 * nf],     A, Y[0], Y[1]);
                    MMA_BF16(acc2[2 * nf + 1], A, Y[2], Y[3]);
                }
            }
        }
        __syncthreads();   // GEMM2 done: mask/yT/nodes smem free

        // ---- issue cp.async mask(c+ZS): lands during next GEMM1 ----
        if (c + ZS < NCHK) {
            const int nn = (c + ZS) * NC;
            #pragma unroll
            for (int i = 0; i < 4; i++) {
                int o = tid + i * 512;
                int row = o >> 3, seg = o & 7;
                CP16(sb + OFF_MK + row * MK_STRIDE + seg * 16,
                     (const char*)(mask + (size_t)row * Nn + nn) + seg * 16);
            }
            CP_COMMIT();
        }
    }

    // ---- drain: atomic-accumulate split-K partials ----
    {
        const int r = wid * 16 + g;
        #pragma unroll
        for (int j = 0; j < 16; j++) {
            const int cb = d0 + j * 8 + 2 * tg;
            atomicAdd(out + (size_t)r * DK + cb,           acc2[j][0]);
            atomicAdd(out + (size_t)r * DK + cb + 1,       acc2[j][1]);
            atomicAdd(out + (size_t)(r + 8) * DK + cb,     acc2[j][2]);
            atomicAdd(out + (size_t)(r + 8) * DK + cb + 1, acc2[j][3]);
        }
    }
}

__global__ void kzero(float* __restrict__ o, int n) {
    const int i = blockIdx.x * 256 + threadIdx.x;
    if (i < n) o[i] = 0.f;
}

extern "C" void kernel_launch(void* const* d_in, const int* in_sizes, int n_in,
                              void* d_out, int out_size)
{
    const float* nodes = (const float*)d_in[0];
    const int*   mask  = (const int*)  d_in[1];
    const float* Wt    = (const float*)d_in[2];
    const float* bt    = (const float*)d_in[3];
    const float* Wg    = (const float*)d_in[4];
    const float* bg    = (const float*)d_in[5];
    float* out = (float*)d_out;

    const int Nn = in_sizes[0] / DK;   // 200000

    cudaFuncSetAttribute(fused_agg, cudaFuncAttributeMaxDynamicSharedMemorySize, SMEM_TOTAL);

    kzero<<<(out_size + 255) / 256, 256>>>(out, out_size);
    fused_agg<<<dim3(ZS, 2), 512, SMEM_TOTAL>>>(nodes, mask, Wt, bt, Wg, bg, out, Nn);
}